// round 8
// baseline (speedup 1.0000x reference)
#include <cuda_runtime.h>
#include <cuda_bf16.h>
#include <cstdint>

// Problem constants (fixed by setup_inputs)
#define NUM_NEW 50000
#define D_MODEL 3584
#define D_ENC   128
#define NB      2048      // batch / segments
#define SEG     32        // tokens per segment
#define CDIM    64        // dims per chunk pass (D_MODEL = 56 * 64)
#define NCP     28        // chunk-pairs (2 * CDIM per block)
#define G       32        // segments per block
#define NGRP    (NB / G)  // 64 groups

// ---------------------------------------------------------------------------
// Fully fused kernel: embedding gather + segment mean + projection.
// grid = (28 chunk-pairs, 64 segment-groups), block = 256 (8 warps), 3 CTAs/SM.
//
// R8 changes vs R7 (149.8us, DRAM=72.3%, occ=24.4%):
//  - W is read straight from L2 in the matvec (warp-uniform __ldg float2,
//    W is 1.8MB -> L2-resident). Removes the 32KB Ws smem stage + one sync.
//  - smem 45KB -> 12.3KB, __launch_bounds__(256,3): 3 CTAs/SM (occ 37.5%)
//    so >=2 CTAs are in gather phase at any time -> higher DRAM duty.
// ---------------------------------------------------------------------------
__global__ __launch_bounds__(256, 3) void fused_gather_proj_kernel(
    const int*   __restrict__ flat_idx,
    const int*   __restrict__ lens,
    const float* __restrict__ embed,
    const float* __restrict__ W,
    const float* __restrict__ bias,
    float*       __restrict__ out)
{
    __shared__ float means[G][CDIM];       // 8 KB
    __shared__ int   idx_s[G * SEG];       // 4 KB

    const int grp  = blockIdx.y;
    const int t    = threadIdx.x;
    const int w    = t >> 5;
    const int lane = t & 31;

    // output-tile mapping for matvec/epilogue:
    // thread -> (n-pair np, segment-group sg). Whole warp shares one sg ->
    // means[.][d] reads are warp-broadcast (conflict-free).
    const int np = t & 63;    // n = np*2, np*2+1
    const int sg = t >> 6;    // segments sg*8 .. sg*8+7

    // Load the group's 1024 token indices (contiguous, seg-major)
    {
        const int base = grp * (G * SEG);
        #pragma unroll
        for (int i = 0; i < (G * SEG) / 256; i++)
            idx_s[t + i * 256] = flat_idx[base + t + i * 256];
    }

    float acc[8][2];
    #pragma unroll
    for (int j = 0; j < 8; j++) { acc[j][0] = 0.f; acc[j][1] = 0.f; }

    #pragma unroll 1
    for (int cp = 0; cp < 2; cp++) {
        const int chunk = blockIdx.x * 2 + cp;

        __syncthreads();  // cp0: idx_s ready; cp1: previous matvec done

        // Gather + mean: warp w handles segments w, w+8, w+16, w+24.
        // Each lane accumulates a float2 (256B coalesced per token row).
        {
            const int doff = chunk * CDIM + lane * 2;
            #pragma unroll 1
            for (int r = 0; r < 4; r++) {
                const int s = w + r * 8;
                float ax = 0.f, ay = 0.f;
                #pragma unroll
                for (int tok = 0; tok < SEG; tok++) {
                    const int idx = idx_s[s * SEG + tok];
                    const float2 v = __ldg(reinterpret_cast<const float2*>(
                        embed + (size_t)idx * D_MODEL + doff));
                    ax += v.x; ay += v.y;
                }
                const float inv = 1.0f / (float)__ldg(&lens[grp * G + s]);
                *reinterpret_cast<float2*>(&means[s][lane * 2]) =
                    make_float2(ax * inv, ay * inv);
            }
        }
        __syncthreads();  // means ready

        // Matvec: acc[j] += means[sg*8+j][d] * W[chunk*CDIM+d][np*2..+1]
        // W read from L2 (warp-uniform address), unroll 8 for MLP.
        {
            const float* Wc = W + (size_t)chunk * CDIM * D_ENC + np * 2;
            #pragma unroll 1
            for (int d0 = 0; d0 < CDIM; d0 += 8) {
                float2 wv[8];
                #pragma unroll
                for (int dd = 0; dd < 8; dd++)
                    wv[dd] = __ldg(reinterpret_cast<const float2*>(
                        Wc + (size_t)(d0 + dd) * D_ENC));
                #pragma unroll
                for (int dd = 0; dd < 8; dd++) {
                    #pragma unroll
                    for (int j = 0; j < 8; j++) {
                        const float m = means[sg * 8 + j][d0 + dd];  // broadcast
                        acc[j][0] = fmaf(m, wv[dd].x, acc[j][0]);
                        acc[j][1] = fmaf(m, wv[dd].y, acc[j][1]);
                    }
                }
            }
        }
    }

    // Epilogue: atomic accumulate (28 chunk-pair blocks per output element).
    // Chunk-pair 0 adds the bias.
    const bool add_bias = (blockIdx.x == 0);
    const int  n  = np * 2;
    const float b0 = add_bias ? bias[n]     : 0.f;
    const float b1 = add_bias ? bias[n + 1] : 0.f;
    #pragma unroll
    for (int j = 0; j < 8; j++) {
        const int s = grp * G + sg * 8 + j;
        atomicAdd(&out[(size_t)s * D_ENC + n],     acc[j][0] + b0);
        atomicAdd(&out[(size_t)s * D_ENC + n + 1], acc[j][1] + b1);
    }
}

// ---------------------------------------------------------------------------
// Launch.  Inputs (metadata order):
//   0: flat_idx int32 [65536]   1: seg int32 [65536]   2: lens int32 [2048]
//   3: embed_weight f32 [50000*3584]  4: proj_w f32 [3584*128]  5: proj_b f32 [128]
// Output: f32 [2048*128]
// ---------------------------------------------------------------------------
extern "C" void kernel_launch(void* const* d_in, const int* in_sizes, int n_in,
                              void* d_out, int out_size)
{
    const int*   flat_idx = (const int*)d_in[0];
    const int*   lens     = (const int*)d_in[2];
    const float* embed    = (const float*)d_in[3];
    const float* proj_w   = (const float*)d_in[4];
    const float* proj_b   = (const float*)d_in[5];
    float*       out      = (float*)d_out;

    // zero output (atomics accumulate; bias added by chunk-pair 0)
    cudaMemsetAsync(out, 0, (size_t)NB * D_ENC * sizeof(float));

    fused_gather_proj_kernel<<<dim3(NCP, NGRP), 256>>>(
        flat_idx, lens, embed, proj_w, proj_b, out);
}

// round 9
// speedup vs baseline: 1.0885x; 1.0885x over previous
#include <cuda_runtime.h>
#include <cuda_bf16.h>
#include <cstdint>

// Problem constants (fixed by setup_inputs)
#define NUM_NEW 50000
#define D_MODEL 3584
#define D_ENC   128
#define NB      2048      // batch / segments
#define SEG     32        // tokens per segment
#define CDIM    64        // dims per chunk (D_MODEL = 56 * 64)
#define NCP     28        // chunk-pairs (block covers 2 chunks = 128 dims)
#define G       32        // segments per block
#define NGRP    (NB / G)  // 64 groups

// ---------------------------------------------------------------------------
// Fully fused kernel with intra-CTA pipelining:
//   gather(c0) -> [gather(c1) || matvec(c0)] -> matvec(c1) -> atomics
// grid = (28, 64), block = 256 (8 warps), 2 CTAs/SM (smem 84KB).
//
// R9 vs R7 (149.8us, DRAM 72.3%): the 4 segment-rounds of gather(c1) are
// source-interleaved with 16-d slices of matvec(c0), so LDG latency is
// filled with FFMA/LDS instead of stalling -> higher DRAM duty.
// ---------------------------------------------------------------------------
__global__ __launch_bounds__(256, 2) void fused_gather_proj_kernel(
    const int*   __restrict__ flat_idx,
    const int*   __restrict__ lens,
    const float* __restrict__ embed,
    const float* __restrict__ W,
    const float* __restrict__ bias,
    float*       __restrict__ out)
{
    __shared__ float Ws[2][CDIM][D_ENC];   // 64 KB (both chunks of the pair)
    __shared__ float means[2][G][CDIM];    // 16 KB (double buffer)
    __shared__ int   idx_s[G * SEG];       // 4 KB

    const int grp  = blockIdx.y;
    const int t    = threadIdx.x;
    const int w    = t >> 5;
    const int lane = t & 31;

    // matvec mapping: warp-uniform segment group, per-thread n-pair
    const int np = t & 63;    // n = np*2, np*2+1
    const int sg = t >> 6;    // segments sg*8 .. sg*8+7

    // Stage indices + both W slices
    {
        const int base = grp * (G * SEG);
        #pragma unroll
        for (int i = 0; i < (G * SEG) / 256; i++)
            idx_s[t + i * 256] = flat_idx[base + t + i * 256];

        const float* Wc = W + (size_t)blockIdx.x * 2 * CDIM * D_ENC;
        float* Wd = &Ws[0][0][0];
        #pragma unroll
        for (int i = 0; i < (2 * CDIM * D_ENC) / (256 * 4); i++) {  // 16 iters
            const int e = (t + i * 256) * 4;
            *reinterpret_cast<float4*>(Wd + e) =
                *reinterpret_cast<const float4*>(Wc + e);
        }
    }
    __syncthreads();

    float acc[8][2];
    #pragma unroll
    for (int j = 0; j < 8; j++) { acc[j][0] = 0.f; acc[j][1] = 0.f; }

    const int c0 = blockIdx.x * 2;

    // ---- Phase 1: gather chunk 0 -> means[0] ----
    {
        const int doff = c0 * CDIM + lane * 2;
        #pragma unroll 1
        for (int r = 0; r < 4; r++) {
            const int s = w + r * 8;
            float ax = 0.f, ay = 0.f;
            #pragma unroll
            for (int tok = 0; tok < SEG; tok++) {
                const int idx = idx_s[s * SEG + tok];
                const float2 v = __ldg(reinterpret_cast<const float2*>(
                    embed + (size_t)idx * D_MODEL + doff));
                ax += v.x; ay += v.y;
            }
            const float inv = 1.0f / (float)__ldg(&lens[grp * G + s]);
            *reinterpret_cast<float2*>(&means[0][s][lane * 2]) =
                make_float2(ax * inv, ay * inv);
        }
    }
    __syncthreads();

    // ---- Phase 2: gather chunk 1 (4 rounds) interleaved with matvec(c0) ----
    {
        const int doff = (c0 + 1) * CDIM + lane * 2;
        #pragma unroll 1
        for (int r = 0; r < 4; r++) {
            const int s = w + r * 8;
            // independent LDG stream (means[1] write at the end)
            float ax = 0.f, ay = 0.f;
            #pragma unroll
            for (int tok = 0; tok < SEG; tok++) {
                const int idx = idx_s[s * SEG + tok];
                const float2 v = __ldg(reinterpret_cast<const float2*>(
                    embed + (size_t)idx * D_MODEL + doff));
                ax += v.x; ay += v.y;
            }

            // matvec(c0) slice: d in [16r, 16r+16), fills the LDG latency
            #pragma unroll
            for (int half = 0; half < 2; half++) {
                const int d0 = r * 16 + half * 8;
                float2 wv[8];
                #pragma unroll
                for (int dd = 0; dd < 8; dd++)
                    wv[dd] = *reinterpret_cast<const float2*>(&Ws[0][d0 + dd][np * 2]);
                #pragma unroll
                for (int j = 0; j < 8; j++) {
                    const float2* mrow = reinterpret_cast<const float2*>(&means[0][sg * 8 + j][d0]);
                    #pragma unroll
                    for (int p = 0; p < 4; p++) {
                        const float2 mv = mrow[p];  // warp-broadcast LDS
                        acc[j][0] = fmaf(mv.x, wv[2*p].x,   acc[j][0]);
                        acc[j][1] = fmaf(mv.x, wv[2*p].y,   acc[j][1]);
                        acc[j][0] = fmaf(mv.y, wv[2*p+1].x, acc[j][0]);
                        acc[j][1] = fmaf(mv.y, wv[2*p+1].y, acc[j][1]);
                    }
                }
            }

            const float inv = 1.0f / (float)__ldg(&lens[grp * G + s]);
            *reinterpret_cast<float2*>(&means[1][s][lane * 2]) =
                make_float2(ax * inv, ay * inv);
        }
    }
    __syncthreads();

    // ---- Phase 3: matvec chunk 1 (tail; covered by co-resident CTA gather) ----
    {
        #pragma unroll 1
        for (int d0 = 0; d0 < CDIM; d0 += 8) {
            float2 wv[8];
            #pragma unroll
            for (int dd = 0; dd < 8; dd++)
                wv[dd] = *reinterpret_cast<const float2*>(&Ws[1][d0 + dd][np * 2]);
            #pragma unroll
            for (int j = 0; j < 8; j++) {
                const float2* mrow = reinterpret_cast<const float2*>(&means[1][sg * 8 + j][d0]);
                #pragma unroll
                for (int p = 0; p < 4; p++) {
                    const float2 mv = mrow[p];
                    acc[j][0] = fmaf(mv.x, wv[2*p].x,   acc[j][0]);
                    acc[j][1] = fmaf(mv.x, wv[2*p].y,   acc[j][1]);
                    acc[j][0] = fmaf(mv.y, wv[2*p+1].x, acc[j][0]);
                    acc[j][1] = fmaf(mv.y, wv[2*p+1].y, acc[j][1]);
                }
            }
        }
    }

    // ---- Epilogue: atomic accumulate (+bias from chunk-pair 0) ----
    const bool add_bias = (blockIdx.x == 0);
    const int  n  = np * 2;
    const float b0 = add_bias ? bias[n]     : 0.f;
    const float b1 = add_bias ? bias[n + 1] : 0.f;
    #pragma unroll
    for (int j = 0; j < 8; j++) {
        const int s = grp * G + sg * 8 + j;
        atomicAdd(&out[(size_t)s * D_ENC + n],     acc[j][0] + b0);
        atomicAdd(&out[(size_t)s * D_ENC + n + 1], acc[j][1] + b1);
    }
}

// ---------------------------------------------------------------------------
// Launch.  Inputs (metadata order):
//   0: flat_idx int32 [65536]   1: seg int32 [65536]   2: lens int32 [2048]
//   3: embed_weight f32 [50000*3584]  4: proj_w f32 [3584*128]  5: proj_b f32 [128]
// Output: f32 [2048*128]
// ---------------------------------------------------------------------------
extern "C" void kernel_launch(void* const* d_in, const int* in_sizes, int n_in,
                              void* d_out, int out_size)
{
    const int*   flat_idx = (const int*)d_in[0];
    const int*   lens     = (const int*)d_in[2];
    const float* embed    = (const float*)d_in[3];
    const float* proj_w   = (const float*)d_in[4];
    const float* proj_b   = (const float*)d_in[5];
    float*       out      = (float*)d_out;

    // zero output (atomics accumulate; bias added by chunk-pair 0)
    cudaMemsetAsync(out, 0, (size_t)NB * D_ENC * sizeof(float));

    fused_gather_proj_kernel<<<dim3(NCP, NGRP), 256>>>(
        flat_idx, lens, embed, proj_w, proj_b, out);
}

// round 10
// speedup vs baseline: 1.3602x; 1.2497x over previous
#include <cuda_runtime.h>
#include <cuda_bf16.h>
#include <cstdint>

// Problem constants (fixed by setup_inputs)
#define NUM_NEW 50000
#define D_MODEL 3584
#define D_ENC   128
#define NB      2048      // batch / segments
#define SEG     32        // tokens per segment
#define CDIM    64        // dims per chunk pass (D_MODEL = 56 * 64)
#define NCP     28        // chunk-pairs (2 * CDIM per block)
#define G       32        // segments per block
#define NGRP    (NB / G)  // 64 groups

// ---------------------------------------------------------------------------
// Fully fused kernel: embedding gather + segment mean + projection.
// grid = (64 groups, 28 chunk-pairs)  <-- R10: axes SWAPPED vs R7.
//
// Why: flat_idx has ~36.5K unique rows out of 65536 draws (1.79x reuse).
// With group as the FAST grid axis, the ~296 co-resident CTAs cover all 64
// groups of the same chunk-pair; that chunk-pair's unique slice set is
// ~36.5K rows x 512B = 18.7MB -> L2-resident. Duplicate token reads hit L2
// instead of DRAM: DRAM traffic 939MB -> ~540MB.
// Kernel body is identical to R7 (149.8us best).
// ---------------------------------------------------------------------------
__global__ __launch_bounds__(256, 2) void fused_gather_proj_kernel(
    const int*   __restrict__ flat_idx,
    const int*   __restrict__ lens,
    const float* __restrict__ embed,
    const float* __restrict__ W,
    const float* __restrict__ bias,
    float*       __restrict__ out)
{
    __shared__ float Ws[CDIM][D_ENC];      // 32 KB, reloaded per chunk pass
    __shared__ float means[G][CDIM];       // 8 KB
    __shared__ int   idx_s[G * SEG];       // 4 KB

    const int grp  = blockIdx.x;           // fast axis: groups
    const int cpair = blockIdx.y;          // slow axis: chunk-pairs
    const int t    = threadIdx.x;
    const int w    = t >> 5;
    const int lane = t & 31;

    // output-tile mapping for the matvec/epilogue
    const int np = t & 63;    // n-pair index: n = np*2, np*2+1
    const int sg = t >> 6;    // 0..3 -> segments sg*8 .. sg*8+7

    // Load the group's 1024 token indices (contiguous, seg-major)
    {
        const int base = grp * (G * SEG);
        #pragma unroll
        for (int i = 0; i < (G * SEG) / 256; i++)
            idx_s[t + i * 256] = flat_idx[base + t + i * 256];
    }

    float acc[8][2];
    #pragma unroll
    for (int j = 0; j < 8; j++) { acc[j][0] = 0.f; acc[j][1] = 0.f; }

    #pragma unroll 1
    for (int cp = 0; cp < 2; cp++) {
        const int chunk = cpair * 2 + cp;

        __syncthreads();  // cp0: idx ready; cp1: previous matvec done

        // Stage W slice: Ws[d][n] = W[(chunk*CDIM + d) * D_ENC + n]
        {
            const float* Wc = W + (size_t)chunk * CDIM * D_ENC;
            #pragma unroll
            for (int i = 0; i < (CDIM * D_ENC) / (256 * 4); i++) {  // 8 iters
                const int e = (t + i * 256) * 4;
                *reinterpret_cast<float4*>(&Ws[0][0] + e) =
                    *reinterpret_cast<const float4*>(Wc + e);
            }
        }

        // Gather + mean: warp w handles segments w, w+8, w+16, w+24
        {
            const int doff = chunk * CDIM + lane * 2;  // float2 per lane
            #pragma unroll 1
            for (int r = 0; r < 4; r++) {
                const int s = w + r * 8;
                float ax = 0.f, ay = 0.f;
                #pragma unroll
                for (int tok = 0; tok < SEG; tok++) {
                    const int idx = idx_s[s * SEG + tok];
                    const float2 v = __ldg(reinterpret_cast<const float2*>(
                        embed + (size_t)idx * D_MODEL + doff));
                    ax += v.x; ay += v.y;
                }
                const float inv = 1.0f / (float)__ldg(&lens[grp * G + s]);
                *reinterpret_cast<float2*>(&means[s][lane * 2]) =
                    make_float2(ax * inv, ay * inv);
            }
        }
        __syncthreads();  // Ws + means ready

        // Matvec accumulate: acc[j][0..1] += means[sg*8+j][d] * Ws[d][np*2..+1]
        #pragma unroll 8
        for (int d = 0; d < CDIM; d++) {
            const float2 wv = *reinterpret_cast<const float2*>(&Ws[d][np * 2]);
            #pragma unroll
            for (int j = 0; j < 8; j++) {
                const float m = means[sg * 8 + j][d];  // warp broadcast
                acc[j][0] = fmaf(m, wv.x, acc[j][0]);
                acc[j][1] = fmaf(m, wv.y, acc[j][1]);
            }
        }
    }

    // Epilogue: atomic accumulate (28 chunk-pair contributions per element).
    // Chunk-pair 0 also adds the bias.
    const bool add_bias = (cpair == 0);
    const int  n  = np * 2;
    const float b0 = add_bias ? bias[n]     : 0.f;
    const float b1 = add_bias ? bias[n + 1] : 0.f;
    #pragma unroll
    for (int j = 0; j < 8; j++) {
        const int s = grp * G + sg * 8 + j;
        atomicAdd(&out[(size_t)s * D_ENC + n],     acc[j][0] + b0);
        atomicAdd(&out[(size_t)s * D_ENC + n + 1], acc[j][1] + b1);
    }
}

// ---------------------------------------------------------------------------
// Launch.  Inputs (metadata order):
//   0: flat_idx int32 [65536]   1: seg int32 [65536]   2: lens int32 [2048]
//   3: embed_weight f32 [50000*3584]  4: proj_w f32 [3584*128]  5: proj_b f32 [128]
// Output: f32 [2048*128]
// ---------------------------------------------------------------------------
extern "C" void kernel_launch(void* const* d_in, const int* in_sizes, int n_in,
                              void* d_out, int out_size)
{
    const int*   flat_idx = (const int*)d_in[0];
    const int*   lens     = (const int*)d_in[2];
    const float* embed    = (const float*)d_in[3];
    const float* proj_w   = (const float*)d_in[4];
    const float* proj_b   = (const float*)d_in[5];
    float*       out      = (float*)d_out;

    // zero output (atomics accumulate; bias added by chunk-pair 0)
    cudaMemsetAsync(out, 0, (size_t)NB * D_ENC * sizeof(float));

    // grid: (groups fast, chunk-pairs slow) -> co-resident CTAs share a
    // chunk-pair's 18.7MB unique slice set in L2.
    fused_gather_proj_kernel<<<dim3(NGRP, NCP), 256>>>(
        flat_idx, lens, embed, proj_w, proj_b, out);
}